// round 13
// baseline (speedup 1.0000x reference)
#include <cuda_runtime.h>

#define NN   64
#define TT   128
#define NBR  16
#define NB2  32
#define NP   256
#define NS   255
#define BIGF 1e30f
#define FULLMASK 0xFFFFFFFFu

__device__ float g_cost[NN * NB2];
__device__ int   g_cnt[NN];     // arrival counter (zero-init; reset each launch)
__device__ int   g_cnt2[NN];    // read-done counter
__device__ int   g_win[NN];     // 0 = not ready; winner b2+1; -1 = no branch

__global__ __launch_bounds__(256, 8)
void fused_arc_kernel(const float* __restrict__ traj,
                      const float* __restrict__ road,
                      const unsigned char* __restrict__ maskraw,
                      float* __restrict__ out)
{
    __shared__ float rpt[NP * 3];      // road pts AoS [p*3+c]
    __shared__ __align__(16) float tbuf[TT * 3];  // traj pts AoS
    __shared__ float sl[NP];           // fwd seg len (0 invalid); sl[255]=0
    __shared__ float cum[NP];          // inclusive scan of sl; cum_s(i)= i? cum[i-1]:0
    __shared__ float tcs_s[TT];        // inclusive scan of traj seg len
    __shared__ float wsA[8], wsB[8];
    __shared__ float wsum[8];
    __shared__ unsigned long long s_key;   // (d2bits<<32)|segidx
    __shared__ int   s_mn, s_mx;
    __shared__ int   sh_pick, sh_win;

    const int tid  = threadIdx.x;
    const int lane = tid & 31;
    const int w    = tid >> 5;
    const int b    = blockIdx.x;       // undirected branch 0..15
    const int n    = blockIdx.y;

    if (tid == 0) {
        s_key = ~0ull;
        s_mn  = NS;
        s_mx  = 0;
    }

    // ---- Phase 0: all global loads straight to registers (no barrier needed)
    const float* rp = road + (size_t)((n * NBR + b) * NP) * 3;
    const float pax = rp[3 * tid + 0];
    const float pay = rp[3 * tid + 1];
    const float paz = rp[3 * tid + 2];
    float pbx = 0.0f, pby = 0.0f, pbz = 0.0f;
    if (tid < NS) {
        pbx = rp[3 * tid + 3];
        pby = rp[3 * tid + 4];
        pbz = rp[3 * tid + 5];
    }
    // mask dtype: lengths>=2 => element (0,0,1) true. int32 LE => byte[1]==0.
    const bool m32 = (maskraw[1] == 0);
    const size_t me = (size_t)(n * NBR + b) * NP + tid;
    bool mv0 = m32 ? (((const int*)maskraw)[me] != 0) : (maskraw[me] != 0);
    bool mv1 = false;
    if (tid < NS)
        mv1 = m32 ? (((const int*)maskraw)[me + 1] != 0) : (maskraw[me + 1] != 0);

    const float* tp = traj + (size_t)n * TT * 3;
    const float p0x = tp[0], p0y = tp[1], p0z = tp[2];   // broadcast
    float ttx = 0, tty = 0, ttz = 0, tnx = 0, tny = 0, tnz = 0;
    if (tid < TT) {
        ttx = tp[3 * tid + 0]; tty = tp[3 * tid + 1]; ttz = tp[3 * tid + 2];
    }
    if (tid < TT - 1) {
        tnx = tp[3 * tid + 3]; tny = tp[3 * tid + 4]; tnz = tp[3 * tid + 5];
    }

    // smem publishes (consumed after B1)
    rpt[3 * tid + 0] = pax;
    rpt[3 * tid + 1] = pay;
    rpt[3 * tid + 2] = paz;
    if (tid < TT) {
        tbuf[3 * tid + 0] = ttx;
        tbuf[3 * tid + 1] = tty;
        tbuf[3 * tid + 2] = ttz;
    }

    // ---- seglen + traj seglen from registers
    const bool smv = (tid < NS) && mv0 && mv1;
    float slv = 0.0f;
    if (smv) {
        float dx = pbx - pax, dy = pby - pay, dz = pbz - paz;
        slv = sqrtf(dx * dx + dy * dy + dz * dz);
    }
    sl[tid] = slv;
    float tlv = 0.0f;
    if (tid < TT - 1) {
        float dx = tnx - ttx, dy = tny - tty, dz = tnz - ttz;
        tlv = sqrtf(dx * dx + dy * dy + dz * dz);
    }

    // ---- p0->segment d2 from registers; CTA argmin + valid range (pre-barrier atomics)
    float d2 = BIGF;
    if (smv) {
        float svx = pbx - pax, svy = pby - pay, svz = pbz - paz;
        float sd  = fmaxf(svx * svx + svy * svy + svz * svz, 1e-12f);
        float t0  = fminf(fmaxf(((p0x - pax) * svx + (p0y - pay) * svy + (p0z - paz) * svz) / sd, 0.0f), 1.0f);
        float ex = p0x - (pax + t0 * svx);
        float ey = p0y - (pay + t0 * svy);
        float ez = p0z - (paz + t0 * svz);
        d2 = ex * ex + ey * ey + ez * ez;
    }
    {
        unsigned bits = __float_as_uint(d2);            // d2>=0 => order-preserving
        unsigned wmin = __reduce_min_sync(FULLMASK, bits);
        unsigned ball = __ballot_sync(FULLMASK, bits == wmin);
        unsigned vb   = __ballot_sync(FULLMASK, smv);
        if (lane == 0) {
            atomicMin(&s_key, ((unsigned long long)wmin << 32) |
                              (unsigned)((w << 5) + (__ffs(ball) - 1)));
            if (vb) {
                atomicMin(&s_mn, (w << 5) + (__ffs(vb) - 1));
                atomicMax(&s_mx, (w << 5) + (32 - __clz(vb)));
            }
        }
    }

    // ---- joint warp-shuffle inclusive scans (registers)
    float vA = slv, vB = tlv;
    #pragma unroll
    for (int off = 1; off < 32; off <<= 1) {
        float tA = __shfl_up_sync(FULLMASK, vA, off);
        float tB = __shfl_up_sync(FULLMASK, vB, off);
        if (lane >= off) { vA += tA; vB += tB; }
    }
    if (lane == 31) { wsA[w] = vA; wsB[w] = vB; }
    __syncthreads();                                    // B1
    {
        float oA = 0.0f, oB = 0.0f;
        #pragma unroll
        for (int k = 0; k < 7; ++k) {
            if (k < w) { oA += wsA[k]; oB += wsB[k]; }
        }
        cum[tid] = vA + oA;
        if (tid < TT) tcs_s[tid] = vB + oB;
    }
    __syncthreads();                                    // B2

    const int  seg0 = (int)(unsigned)(s_key & 0xFFFFFFFFull);
    const int  fmx  = s_mx;
    const int  fmn  = s_mn;
    const bool has  = (fmx > 0);
    const int  mvjF = has ? (fmx - 1) : 0;
    const int  mvjB = has ? (NS - 1 - fmn) : 0;
    const float total = cum[NP - 1];

    float entryF;
    {
        int k = seg0;
        float ax = rpt[3 * k + 0], ay = rpt[3 * k + 1], az = rpt[3 * k + 2];
        float sx = rpt[3 * k + 3] - ax, sy = rpt[3 * k + 4] - ay, sz = rpt[3 * k + 5] - az;
        float sd = fmaxf(sx * sx + sy * sy + sz * sz, 1e-12f);
        float t0 = fminf(fmaxf(((p0x - ax) * sx + (p0y - ay) * sy + (p0z - az) * sz) / sd, 0.0f), 1.0f);
        entryF = ((k == 0) ? 0.0f : cum[k - 1]) + t0 * sl[k];
    }

    // ---- walks: warps 0-3 fwd (b2=b), warps 4-7 bwd (b2=b+16)
    const bool  isB = (tid >= TT);
    const int   t   = tid & (TT - 1);
    const float entry = isB ? (total - entryF) : entryF;
    const int   mvj   = isB ? mvjB : mvjF;

    float tcv = (t == 0) ? 0.0f : tcs_s[t - 1];
    float tgt = fmaxf(fminf(entry + tcv, total), 0.0f);

    // Clamped-target shortcut (exact; see R11 derivation)
    int j;
    if (__all_sync(FULLMASK, tgt >= total)) {
        j = mvj;
    } else {
        const float T = isB ? (total - tgt) : tgt;
        int k = 0;
        #pragma unroll
        for (int step = 128; step > 0; step >>= 1) {
            int nj = k + step;                   // nj <= 255
            float v = cum[nj - 1];
            bool ok = isB ? (v < T) : (v <= T);  // isB warp-uniform
            if (ok) k = nj;
        }
        j = isB ? ((T > 0.0f) ? (NS - 1 - k) : NS) : k;
        j = min(j, mvj);
    }

    float cj  = (j == 0) ? 0.0f : (isB ? (total - cum[NS - 1 - j]) : cum[j - 1]);
    float slj = isB ? sl[NS - 1 - j] : sl[j];
    float tl  = fminf(fmaxf((tgt - cj) / fmaxf(slj, 1e-9f), 0.0f), 1.0f);
    float prx, pry, prz;
    if (isB) {
        int r = NP - 1 - j;                  // a_bw[j]=P[255-j], next=P[254-j]
        float ax = rpt[3 * r + 0], ay = rpt[3 * r + 1], az = rpt[3 * r + 2];
        prx = ax + tl * (rpt[3 * r - 3] - ax);
        pry = ay + tl * (rpt[3 * r - 2] - ay);
        prz = az + tl * (rpt[3 * r - 1] - az);
    } else {
        float ax = rpt[3 * j + 0], ay = rpt[3 * j + 1], az = rpt[3 * j + 2];
        prx = ax + tl * (rpt[3 * j + 3] - ax);
        pry = ay + tl * (rpt[3 * j + 4] - ay);
        prz = az + tl * (rpt[3 * j + 5] - az);
    }
    // projections stay in registers — no g_proj traffic

    float dx = tbuf[3 * t + 0] - prx;
    float dy = tbuf[3 * t + 1] - pry;
    float dz = tbuf[3 * t + 2] - prz;
    float dist = sqrtf(dx * dx + dy * dy + dz * dz);

    // deterministic dist sums (warp shfl + fixed-order combine)
    #pragma unroll
    for (int off = 16; off > 0; off >>= 1)
        dist += __shfl_xor_sync(FULLMASK, dist, off);
    if (lane == 0) wsum[w] = dist;
    __syncthreads();                                    // B3

    if (tid == 0) {
        float cf = wsum[0] + wsum[1] + wsum[2] + wsum[3];
        float cb = wsum[4] + wsum[5] + wsum[6] + wsum[7];
        g_cost[n * NB2 + b]       = has ? cf : BIGF;
        g_cost[n * NB2 + b + NBR] = has ? cb : BIGF;
        __threadfence();                       // release g_cost
        int old = atomicAdd(&g_cnt[n], 1);
        sh_pick = (old == NBR - 1);
    }
    __syncthreads();                                    // B4

    if (sh_pick) {
        // ---- picker: 32-way argmin over costs, publish winner flag
        __threadfence();                       // acquire g_cost
        if (w == 0) {
            float cv = __ldcg(&g_cost[n * NB2 + lane]);
            float pbd = cv; int pbi = lane;
            #pragma unroll
            for (int off = 16; off > 0; off >>= 1) {
                float od = __shfl_xor_sync(FULLMASK, pbd, off);
                int   oi = __shfl_xor_sync(FULLMASK, pbi, off);
                if (od < pbd || (od == pbd && oi < pbi)) { pbd = od; pbi = oi; }
            }
            if (lane == 0)
                sh_win = (pbd < BIGF) ? (pbi + 1) : -1;
        }
        __syncthreads();
        if (sh_win < 0 && tid < 96) {         // no branch: traj passthrough
            ((float4*)(out + (size_t)n * TT * 3))[tid] = ((const float4*)tbuf)[tid];
        }
        if (tid == 0)
            atomicExch(&g_win[n], sh_win);    // publish (device-scope)
    }

    // ---- all CTAs: wait for winner flag (whole grid co-resident: 8 CTAs/SM x 148 >= 1024)
    if (tid == 0) {
        int v = atomicAdd(&g_win[n], 0);
        while (v == 0) {
            __nanosleep(128);
            v = atomicAdd(&g_win[n], 0);
        }
        sh_win = v;
    }
    __syncthreads();                                    // B5

    const int win = sh_win;
    if (win > 0) {
        const int wb2 = win - 1;
        if ((wb2 & (NBR - 1)) == b && (wb2 >= NBR) == isB) {
            // this CTA half owns the winning branch: write out from registers
            size_t oo = (size_t)(n * TT + t) * 3;
            out[oo + 0] = prx;
            out[oo + 1] = pry;
            out[oo + 2] = prz;
        }
    }

    if (tid == 0) {
        int old2 = atomicAdd(&g_cnt2[n], 1);
        if (old2 == NBR - 1) {                 // last reader resets for next replay
            g_cnt[n]  = 0;
            g_cnt2[n] = 0;
            g_win[n]  = 0;
            __threadfence();
        }
    }
}

extern "C" void kernel_launch(void* const* d_in, const int* in_sizes, int n_in,
                              void* d_out, int out_size)
{
    const float*         traj = (const float*)d_in[0];
    const float*         road = (const float*)d_in[1];
    const unsigned char* mask = (const unsigned char*)d_in[2];
    float* out = (float*)d_out;

    dim3 grid(NBR, NN);
    fused_arc_kernel<<<grid, 256>>>(traj, road, mask, out);
}

// round 14
// speedup vs baseline: 1.4812x; 1.4812x over previous
#include <cuda_runtime.h>

#define NN   64
#define TT   128
#define NBR  16
#define NB2  32
#define NP   256
#define NS   255
#define BIGF 1e30f
#define FULLMASK 0xFFFFFFFFu

// padded: one float4 per (branch, t) -> single coalesced STG.128 per thread
__device__ __align__(16) float4 g_proj[NN * NB2 * TT];
__device__ float g_cost[NN * NB2];
__device__ int   g_cnt[NN];          // zero-init; picker resets each launch

__global__ __launch_bounds__(256)
void fused_arc_kernel(const float* __restrict__ traj,
                      const float* __restrict__ road,
                      const unsigned char* __restrict__ maskraw,
                      float* __restrict__ out)
{
    __shared__ float rpt[NP * 3];      // road pts AoS [p*3+c]
    __shared__ __align__(16) float tbuf[TT * 3];  // traj pts AoS
    __shared__ __align__(16) float stg[TT * 3];   // picker de-pad staging
    __shared__ float sl[NP];           // fwd seg len (0 invalid); sl[255]=0
    __shared__ float cum[NP];          // inclusive scan of sl; cum_s(i)= i? cum[i-1]:0
    __shared__ float tcs_s[TT];        // inclusive scan of traj seg len
    __shared__ float wsA[8], wsB[8];
    __shared__ float wsum[8];
    __shared__ unsigned long long s_key;   // (d2bits<<32)|segidx
    __shared__ int   s_mn, s_mx;
    __shared__ int   sh_pick, sh_b, sh_hasb;

    const int tid  = threadIdx.x;
    const int lane = tid & 31;
    const int w    = tid >> 5;
    const int b    = blockIdx.x;       // undirected branch 0..15
    const int n    = blockIdx.y;

    if (tid == 0) {
        s_key = ~0ull;
        s_mn  = NS;
        s_mx  = 0;
    }

    // ---- Phase 0: all global loads straight to registers (no barrier needed)
    const float* rp = road + (size_t)((n * NBR + b) * NP) * 3;
    const float pax = rp[3 * tid + 0];
    const float pay = rp[3 * tid + 1];
    const float paz = rp[3 * tid + 2];
    float pbx = 0.0f, pby = 0.0f, pbz = 0.0f;
    if (tid < NS) {                      // guard: last thread would read OOB
        pbx = rp[3 * tid + 3];
        pby = rp[3 * tid + 4];
        pbz = rp[3 * tid + 5];
    }
    // mask dtype: lengths>=2 => element (0,0,1) true. int32 LE => byte[1]==0.
    const bool m32 = (maskraw[1] == 0);
    const size_t me = (size_t)(n * NBR + b) * NP + tid;
    bool mv0 = m32 ? (((const int*)maskraw)[me] != 0) : (maskraw[me] != 0);
    bool mv1 = false;
    if (tid < NS)
        mv1 = m32 ? (((const int*)maskraw)[me + 1] != 0) : (maskraw[me + 1] != 0);

    const float* tp = traj + (size_t)n * TT * 3;
    const float p0x = tp[0], p0y = tp[1], p0z = tp[2];   // broadcast
    float ttx = 0, tty = 0, ttz = 0, tnx = 0, tny = 0, tnz = 0;
    if (tid < TT) {
        ttx = tp[3 * tid + 0]; tty = tp[3 * tid + 1]; ttz = tp[3 * tid + 2];
    }
    if (tid < TT - 1) {
        tnx = tp[3 * tid + 3]; tny = tp[3 * tid + 4]; tnz = tp[3 * tid + 5];
    }

    // smem publishes (consumed after B1)
    rpt[3 * tid + 0] = pax;
    rpt[3 * tid + 1] = pay;
    rpt[3 * tid + 2] = paz;
    if (tid < TT) {
        tbuf[3 * tid + 0] = ttx;
        tbuf[3 * tid + 1] = tty;
        tbuf[3 * tid + 2] = ttz;
    }

    // ---- seglen + traj seglen from registers
    const bool smv = (tid < NS) && mv0 && mv1;
    float slv = 0.0f;
    if (smv) {
        float dx = pbx - pax, dy = pby - pay, dz = pbz - paz;
        slv = sqrtf(dx * dx + dy * dy + dz * dz);
    }
    sl[tid] = slv;
    float tlv = 0.0f;
    if (tid < TT - 1) {
        float dx = tnx - ttx, dy = tny - tty, dz = tnz - ttz;
        tlv = sqrtf(dx * dx + dy * dy + dz * dz);
    }

    // ---- p0->segment d2 from registers; CTA argmin + valid range (pre-barrier atomics)
    float d2 = BIGF;
    if (smv) {
        float svx = pbx - pax, svy = pby - pay, svz = pbz - paz;
        float sd  = fmaxf(svx * svx + svy * svy + svz * svz, 1e-12f);
        float t0  = fminf(fmaxf(((p0x - pax) * svx + (p0y - pay) * svy + (p0z - paz) * svz) / sd, 0.0f), 1.0f);
        float ex = p0x - (pax + t0 * svx);
        float ey = p0y - (pay + t0 * svy);
        float ez = p0z - (paz + t0 * svz);
        d2 = ex * ex + ey * ey + ez * ez;
    }
    {
        unsigned bits = __float_as_uint(d2);            // d2>=0 => order-preserving
        unsigned wmin = __reduce_min_sync(FULLMASK, bits);
        unsigned ball = __ballot_sync(FULLMASK, bits == wmin);
        unsigned vb   = __ballot_sync(FULLMASK, smv);
        if (lane == 0) {
            atomicMin(&s_key, ((unsigned long long)wmin << 32) |
                              (unsigned)((w << 5) + (__ffs(ball) - 1)));
            if (vb) {
                atomicMin(&s_mn, (w << 5) + (__ffs(vb) - 1));
                atomicMax(&s_mx, (w << 5) + (32 - __clz(vb)));
            }
        }
    }

    // ---- joint warp-shuffle inclusive scans (registers)
    float vA = slv, vB = tlv;
    #pragma unroll
    for (int off = 1; off < 32; off <<= 1) {
        float tA = __shfl_up_sync(FULLMASK, vA, off);
        float tB = __shfl_up_sync(FULLMASK, vB, off);
        if (lane >= off) { vA += tA; vB += tB; }
    }
    if (lane == 31) { wsA[w] = vA; wsB[w] = vB; }
    __syncthreads();                                    // B1: rpt/tbuf/sl/wsA/wsB/atomics
    {
        float oA = 0.0f, oB = 0.0f;
        #pragma unroll
        for (int k = 0; k < 7; ++k) {
            if (k < w) { oA += wsA[k]; oB += wsB[k]; }
        }
        cum[tid] = vA + oA;
        if (tid < TT) tcs_s[tid] = vB + oB;
    }
    __syncthreads();                                    // B2: cum/tcs_s published

    const int  seg0 = (int)(unsigned)(s_key & 0xFFFFFFFFull);
    const int  fmx  = s_mx;
    const int  fmn  = s_mn;
    const bool has  = (fmx > 0);
    const int  mvjF = has ? (fmx - 1) : 0;
    const int  mvjB = has ? (NS - 1 - fmn) : 0;
    const float total = cum[NP - 1];

    float entryF;
    {
        int k = seg0;
        float ax = rpt[3 * k + 0], ay = rpt[3 * k + 1], az = rpt[3 * k + 2];
        float sx = rpt[3 * k + 3] - ax, sy = rpt[3 * k + 4] - ay, sz = rpt[3 * k + 5] - az;
        float sd = fmaxf(sx * sx + sy * sy + sz * sz, 1e-12f);
        float t0 = fminf(fmaxf(((p0x - ax) * sx + (p0y - ay) * sy + (p0z - az) * sz) / sd, 0.0f), 1.0f);
        entryF = ((k == 0) ? 0.0f : cum[k - 1]) + t0 * sl[k];
    }

    // ---- walks: warps 0-3 fwd (b2=b), warps 4-7 bwd (b2=b+16)
    const bool  isB = (tid >= TT);
    const int   t   = tid & (TT - 1);
    const float entry = isB ? (total - entryF) : entryF;
    const int   mvj   = isB ? mvjB : mvjF;

    float tcv = (t == 0) ? 0.0f : tcs_s[t - 1];
    float tgt = fmaxf(fminf(entry + tcv, total), 0.0f);

    // Clamped-target shortcut (exact): tgt == total
    //   fwd: largest k with cum_s(k) <= total is 255 -> j = min(255,mvj) = mvj
    //   bwd: T = 0, no k with cum_s(k) < 0 -> k=0 -> j = 255 -> min = mvj
    int j;
    if (__all_sync(FULLMASK, tgt >= total)) {
        j = mvj;
    } else {
        //  fwd: largest k with cum_s(k) <= tgt
        //  bwd: largest k with cum_s(k) <  u (u = total - tgt); j = u>0 ? 254-k : 255
        const float T = isB ? (total - tgt) : tgt;
        int k = 0;
        #pragma unroll
        for (int step = 128; step > 0; step >>= 1) {
            int nj = k + step;                   // nj <= 255
            float v = cum[nj - 1];
            bool ok = isB ? (v < T) : (v <= T);  // isB warp-uniform
            if (ok) k = nj;
        }
        j = isB ? ((T > 0.0f) ? (NS - 1 - k) : NS) : k;
        j = min(j, mvj);
    }

    float cj  = (j == 0) ? 0.0f : (isB ? (total - cum[NS - 1 - j]) : cum[j - 1]);
    float slj = isB ? sl[NS - 1 - j] : sl[j];
    float tl  = fminf(fmaxf((tgt - cj) / fmaxf(slj, 1e-9f), 0.0f), 1.0f);
    float prx, pry, prz;
    if (isB) {
        int r = NP - 1 - j;                  // a_bw[j]=P[255-j], next=P[254-j]
        float ax = rpt[3 * r + 0], ay = rpt[3 * r + 1], az = rpt[3 * r + 2];
        prx = ax + tl * (rpt[3 * r - 3] - ax);
        pry = ay + tl * (rpt[3 * r - 2] - ay);
        prz = az + tl * (rpt[3 * r - 1] - az);
    } else {
        float ax = rpt[3 * j + 0], ay = rpt[3 * j + 1], az = rpt[3 * j + 2];
        prx = ax + tl * (rpt[3 * j + 3] - ax);
        pry = ay + tl * (rpt[3 * j + 4] - ay);
        prz = az + tl * (rpt[3 * j + 5] - az);
    }
    // single coalesced STG.128 per thread (padded layout)
    g_proj[(size_t)(n * NB2 + (isB ? b + NBR : b)) * TT + t] =
        make_float4(prx, pry, prz, 0.0f);

    float dx = tbuf[3 * t + 0] - prx;
    float dy = tbuf[3 * t + 1] - pry;
    float dz = tbuf[3 * t + 2] - prz;
    float dist = sqrtf(dx * dx + dy * dy + dz * dz);

    // deterministic dist sums (warp shfl + fixed-order combine)
    #pragma unroll
    for (int off = 16; off > 0; off >>= 1)
        dist += __shfl_xor_sync(FULLMASK, dist, off);
    if (lane == 0) wsum[w] = dist;
    __syncthreads();                                    // B3

    if (tid == 0) {
        float cf = wsum[0] + wsum[1] + wsum[2] + wsum[3];
        float cb = wsum[4] + wsum[5] + wsum[6] + wsum[7];
        g_cost[n * NB2 + b]       = has ? cf : BIGF;
        g_cost[n * NB2 + b + NBR] = has ? cb : BIGF;
        __threadfence();                       // release g_proj + g_cost
        int old = atomicAdd(&g_cnt[n], 1);
        sh_pick = (old == NBR - 1);
    }
    __syncthreads();                                    // B4

    if (!sh_pick) return;

    // ---- picker CTA for sample n: 32-way argmin + de-pad gather
    __threadfence();                           // acquire
    if (w == 0) {
        float cv = __ldcg(&g_cost[n * NB2 + lane]);
        float pbd = cv; int pbi = lane;
        #pragma unroll
        for (int off = 16; off > 0; off >>= 1) {
            float od = __shfl_xor_sync(FULLMASK, pbd, off);
            int   oi = __shfl_xor_sync(FULLMASK, pbi, off);
            if (od < pbd || (od == pbd && oi < pbi)) { pbd = od; pbi = oi; }
        }
        if (lane == 0) { sh_b = pbi; sh_hasb = (pbd < BIGF); }
    }
    __syncthreads();                                    // B5

    if (sh_hasb) {
        if (tid < TT) {
            const float4* gp4 = (const float4*)g_proj + (size_t)(n * NB2 + sh_b) * TT;
            float4 v;
            v.x = __ldcg((const float*)&gp4[tid] + 0);
            v.y = __ldcg((const float*)&gp4[tid] + 1);
            v.z = __ldcg((const float*)&gp4[tid] + 2);
            stg[3 * tid + 0] = v.x;
            stg[3 * tid + 1] = v.y;
            stg[3 * tid + 2] = v.z;
        }
        __syncthreads();                                // B6 (picker only)
        if (tid < 96)
            ((float4*)(out + (size_t)n * TT * 3))[tid] = ((const float4*)stg)[tid];
    } else {
        if (tid < 96)
            ((float4*)(out + (size_t)n * TT * 3))[tid] = ((const float4*)tbuf)[tid];
    }
    if (tid == 0) g_cnt[n] = 0;                // reset for next graph replay
}

extern "C" void kernel_launch(void* const* d_in, const int* in_sizes, int n_in,
                              void* d_out, int out_size)
{
    const float*         traj = (const float*)d_in[0];
    const float*         road = (const float*)d_in[1];
    const unsigned char* mask = (const unsigned char*)d_in[2];
    float* out = (float*)d_out;

    dim3 grid(NBR, NN);
    fused_arc_kernel<<<grid, 256>>>(traj, road, mask, out);
}